// round 12
// baseline (speedup 1.0000x reference)
#include <cuda_runtime.h>
#include <cuda_bf16.h>
#include <cstdint>

// ===========================================================================
// MTLoRALinear on sm_103a — legacy-tensor-pipe bf16 3-term.
// R12 = R11 (BM128 BN256 BK64, 2x96KB cp.async, ldsm4) + fragment-level
//       software pipelining: double-buffered B fragments (B(jp+1) loads issue
//       before MMAs of jp) and term-outer MMA order (same-accumulator
//       distance 4 -> 8).
//   prep_wk : W fp32 -> bf16 hi/lo
//   lora_y  : Y[M,80] = x @ concat(A_sh,A_tasks)^T (tf32) AND x -> bf16 hi/lo
//   fused   : P = x@W^T via 3-term bf16 m16n8k16 (hh+hl+lh); epilogue: bias +
//             5 rank-16 tf32 corrections + streamed stores.
// ===========================================================================

namespace {
constexpr int MTOT = 32768, DK = 1024, OK = 1024;
constexpr int BM = 128, BN = 256, BK = 64;
constexpr int NCHUNK = DK / BK;           // 16
constexpr int NSTAGE = 2;
// stage layout (128B rows): xhi(16K) xlo(16K) whi(32K) wlo(32K) = 96KB
constexpr int OFF_XHI = 0, OFF_XLO = 16384, OFF_WHI = 32768, OFF_WLO = 65536;
constexpr int STAGE_B = 98304;
constexpr int SMEM_DYN = NSTAGE * STAGE_B + 1024;   // 197632
constexpr int XST = 36;                   // lora_y smem stride
constexpr int EST = 84;                   // epilogue stride (conflict-free)
constexpr int EPI_B_OFF = 43520;          // Ys: 128*84*4=43008, Bs after
}

__device__ __align__(256) __nv_bfloat16 g_xhi[MTOT * DK];
__device__ __align__(256) __nv_bfloat16 g_xlo[MTOT * DK];
__device__ __align__(256) __nv_bfloat16 g_whi[OK * DK];
__device__ __align__(256) __nv_bfloat16 g_wlo[OK * DK];
__device__ __align__(256) float         g_Y[MTOT * 80];

// --------------------------- helpers ---------------------------------------
__device__ __forceinline__ uint32_t smem_u32(const void* p) {
    uint32_t a;
    asm("{ .reg .u64 t; cvta.to.shared.u64 t, %1; cvt.u32.u64 %0, t; }"
        : "=r"(a) : "l"(p));
    return a;
}
__device__ __forceinline__ void cp16(uint32_t dst, const void* src) {
    asm volatile("cp.async.cg.shared.global [%0], [%1], 16;"
                 :: "r"(dst), "l"(src) : "memory");
}
__device__ __forceinline__ void cp_commit() {
    asm volatile("cp.async.commit_group;" ::: "memory");
}
template <int N> __device__ __forceinline__ void cp_wait() {
    asm volatile("cp.async.wait_group %0;" :: "n"(N) : "memory");
}
__device__ __forceinline__ void ldsm4(uint32_t& r0, uint32_t& r1, uint32_t& r2,
                                      uint32_t& r3, uint32_t a) {
    asm volatile("ldmatrix.sync.aligned.m8n8.x4.shared.b16 {%0,%1,%2,%3}, [%4];"
                 : "=r"(r0), "=r"(r1), "=r"(r2), "=r"(r3) : "r"(a));
}
__device__ __forceinline__ void mma_bf16(float* c, const uint32_t* a,
                                         const uint32_t* b) {
    asm volatile(
        "mma.sync.aligned.m16n8k16.row.col.f32.bf16.bf16.f32 "
        "{%0,%1,%2,%3}, {%4,%5,%6,%7}, {%8,%9}, {%0,%1,%2,%3};"
        : "+f"(c[0]), "+f"(c[1]), "+f"(c[2]), "+f"(c[3])
        : "r"(a[0]), "r"(a[1]), "r"(a[2]), "r"(a[3]), "r"(b[0]), "r"(b[1]));
}
__device__ __forceinline__ uint32_t tf32_rna(float x) {
    uint32_t u;
    asm("cvt.rna.tf32.f32 %0, %1;" : "=r"(u) : "f"(x));
    return u;
}
__device__ __forceinline__ float tf32f(float x) {
    return __uint_as_float(tf32_rna(x));
}
__device__ __forceinline__ void mma_tf32(float* c, const uint32_t* a,
                                         const uint32_t* b) {
    asm volatile(
        "mma.sync.aligned.m16n8k8.row.col.f32.tf32.tf32.f32 "
        "{%0,%1,%2,%3}, {%4,%5,%6,%7}, {%8,%9}, {%0,%1,%2,%3};"
        : "+f"(c[0]), "+f"(c[1]), "+f"(c[2]), "+f"(c[3])
        : "r"(a[0]), "r"(a[1]), "r"(a[2]), "r"(a[3]), "r"(b[0]), "r"(b[1]));
}
__device__ __forceinline__ void mma_tf32_dc(float* d, const float* c,
                                            const uint32_t* a, const uint32_t* b) {
    asm volatile(
        "mma.sync.aligned.m16n8k8.row.col.f32.tf32.tf32.f32 "
        "{%0,%1,%2,%3}, {%4,%5,%6,%7}, {%8,%9}, {%10,%11,%12,%13};"
        : "=f"(d[0]), "=f"(d[1]), "=f"(d[2]), "=f"(d[3])
        : "r"(a[0]), "r"(a[1]), "r"(a[2]), "r"(a[3]), "r"(b[0]), "r"(b[1]),
          "f"(c[0]), "f"(c[1]), "f"(c[2]), "f"(c[3]));
}
__device__ __forceinline__ void split8(const float4& a, const float4& b,
                                       uint4& h, uint4& l) {
    float f[8] = {a.x, a.y, a.z, a.w, b.x, b.y, b.z, b.w};
    uint32_t hp[4], lp[4];
#pragma unroll
    for (int i = 0; i < 4; i++) {
        __nv_bfloat16 h0 = __float2bfloat16_rn(f[2 * i]);
        __nv_bfloat16 h1 = __float2bfloat16_rn(f[2 * i + 1]);
        __nv_bfloat16 l0 = __float2bfloat16_rn(f[2 * i] - __bfloat162float(h0));
        __nv_bfloat16 l1 = __float2bfloat16_rn(f[2 * i + 1] - __bfloat162float(h1));
        hp[i] = (uint32_t)__bfloat16_as_ushort(h0) |
                ((uint32_t)__bfloat16_as_ushort(h1) << 16);
        lp[i] = (uint32_t)__bfloat16_as_ushort(l0) |
                ((uint32_t)__bfloat16_as_ushort(l1) << 16);
    }
    h = make_uint4(hp[0], hp[1], hp[2], hp[3]);
    l = make_uint4(lp[0], lp[1], lp[2], lp[3]);
}
__device__ __forceinline__ void split4(const float4& v, uint2& h, uint2& l) {
    __nv_bfloat16 h0 = __float2bfloat16_rn(v.x), h1 = __float2bfloat16_rn(v.y);
    __nv_bfloat16 h2 = __float2bfloat16_rn(v.z), h3 = __float2bfloat16_rn(v.w);
    __nv_bfloat16 l0 = __float2bfloat16_rn(v.x - __bfloat162float(h0));
    __nv_bfloat16 l1 = __float2bfloat16_rn(v.y - __bfloat162float(h1));
    __nv_bfloat16 l2 = __float2bfloat16_rn(v.z - __bfloat162float(h2));
    __nv_bfloat16 l3 = __float2bfloat16_rn(v.w - __bfloat162float(h3));
    h.x = (uint32_t)__bfloat16_as_ushort(h0) | ((uint32_t)__bfloat16_as_ushort(h1) << 16);
    h.y = (uint32_t)__bfloat16_as_ushort(h2) | ((uint32_t)__bfloat16_as_ushort(h3) << 16);
    l.x = (uint32_t)__bfloat16_as_ushort(l0) | ((uint32_t)__bfloat16_as_ushort(l1) << 16);
    l.y = (uint32_t)__bfloat16_as_ushort(l2) | ((uint32_t)__bfloat16_as_ushort(l3) << 16);
}
// 128B-row tile, 8x16B chunks, XOR-8 swizzle (R4/R11-proven conflict-free)
__device__ __forceinline__ uint32_t tswz64(int row, int ch) {
    return (uint32_t)(row * 128 + ((ch ^ (row & 7)) << 4));
}

// --------------------------- prep W ----------------------------------------
__global__ __launch_bounds__(256) void prep_wk(const float* __restrict__ W) {
    size_t i = ((size_t)blockIdx.x * 256 + threadIdx.x) * 8;
    float4 a = *reinterpret_cast<const float4*>(W + i);
    float4 b = *reinterpret_cast<const float4*>(W + i + 4);
    uint4 h, l;
    split8(a, b, h, l);
    *reinterpret_cast<uint4*>(g_whi + i) = h;
    *reinterpret_cast<uint4*>(g_wlo + i) = l;
}

// ---------------- lora_y + inline x -> bf16 hi/lo split --------------------
__global__ __launch_bounds__(256) void lora_y_kernel(
    const float* __restrict__ x,
    const float* __restrict__ A_sh,
    const float* __restrict__ A_tasks)
{
    __shared__ float Xs[BM * XST];
    __shared__ float Ws[BM * XST];

    const int tid = threadIdx.x;
    const int lane = tid & 31, wid = tid >> 5;
    const int wm = wid >> 2, wn = wid & 3;
    const int m0 = blockIdx.x * BM;
    const int lr = tid >> 3;
    const int lc = (tid & 7) << 2;

    const float* xg = x + (size_t)(m0 + lr) * DK + lc;
    const float* ag[4];
    bool av[4];
#pragma unroll
    for (int i = 0; i < 4; i++) {
        const int r = lr + 32 * i;
        if (r < 16)      { ag[i] = A_sh + (size_t)r * DK + lc; av[i] = true; }
        else if (r < 80) { ag[i] = A_tasks + (size_t)(r - 16) * DK + lc; av[i] = true; }
        else             { ag[i] = A_sh + lc; av[i] = false; }
    }

    float4 px[4], pw[4];
    const float4 z4 = make_float4(0.f, 0.f, 0.f, 0.f);
#pragma unroll
    for (int i = 0; i < 4; i++) {
        px[i] = *reinterpret_cast<const float4*>(xg + (size_t)(32 * i) * DK);
        pw[i] = av[i] ? *reinterpret_cast<const float4*>(ag[i]) : z4;
    }

    float c[4][4][4];
#pragma unroll
    for (int i = 0; i < 4; i++)
#pragma unroll
        for (int j = 0; j < 4; j++)
#pragma unroll
            for (int q = 0; q < 4; q++) c[i][j][q] = 0.f;

    for (int kc = 0; kc < DK; kc += 32) {
        __syncthreads();
#pragma unroll
        for (int i = 0; i < 4; i++) {
            {
                uint2 h, l;
                split4(px[i], h, l);
                const size_t go = (size_t)(m0 + lr + 32 * i) * DK + kc + lc;
                *reinterpret_cast<uint2*>(g_xhi + go) = h;
                *reinterpret_cast<uint2*>(g_xlo + go) = l;
            }
            float* xs = &Xs[(lr + 32 * i) * XST + lc];
            xs[0] = tf32f(px[i].x); xs[1] = tf32f(px[i].y);
            xs[2] = tf32f(px[i].z); xs[3] = tf32f(px[i].w);
            float* ws = &Ws[(lr + 32 * i) * XST + lc];
            ws[0] = tf32f(pw[i].x); ws[1] = tf32f(pw[i].y);
            ws[2] = tf32f(pw[i].z); ws[3] = tf32f(pw[i].w);
        }
        __syncthreads();
        if (kc + 32 < DK) {
#pragma unroll
            for (int i = 0; i < 4; i++) {
                px[i] = *reinterpret_cast<const float4*>(xg + (size_t)(32 * i) * DK + kc + 32);
                pw[i] = av[i] ? *reinterpret_cast<const float4*>(ag[i] + kc + 32) : z4;
            }
        }
#pragma unroll
        for (int ks = 0; ks < 4; ks++) {
            const int ak = ks * 8 + (lane & 3);
            const int ar = wm * 64 + (lane >> 2);
            uint32_t a[4][4];
#pragma unroll
            for (int i = 0; i < 4; i++) {
                const float* base = &Xs[(ar + i * 16) * XST + ak];
                a[i][0] = __float_as_uint(base[0]);
                a[i][1] = __float_as_uint(base[8 * XST]);
                a[i][2] = __float_as_uint(base[4]);
                a[i][3] = __float_as_uint(base[8 * XST + 4]);
            }
            uint32_t b[4][2];
            const int bn = wn * 32 + (lane >> 2);
#pragma unroll
            for (int j = 0; j < 4; j++) {
                const float* base = &Ws[(bn + j * 8) * XST + ak];
                b[j][0] = __float_as_uint(base[0]);
                b[j][1] = __float_as_uint(base[4]);
            }
#pragma unroll
            for (int i = 0; i < 4; i++)
#pragma unroll
                for (int j = 0; j < 4; j++)
                    mma_tf32(c[i][j], a[i], b[j]);
        }
    }

#pragma unroll
    for (int j = 0; j < 4; j++) {
        const int colb = wn * 32 + j * 8 + (lane & 3) * 2;
        if (colb < 80) {
#pragma unroll
            for (int i = 0; i < 4; i++) {
                const int r0 = m0 + wm * 64 + i * 16 + (lane >> 2);
                *reinterpret_cast<float2*>(g_Y + (size_t)r0 * 80 + colb) =
                    make_float2(c[i][j][0], c[i][j][1]);
                *reinterpret_cast<float2*>(g_Y + (size_t)(r0 + 8) * 80 + colb) =
                    make_float2(c[i][j][2], c[i][j][3]);
            }
        }
    }
}

// --------------------------- fused main ------------------------------------
__global__ __launch_bounds__(256, 1) void fused_main(
    const float* __restrict__ bias,
    const float* __restrict__ B_sh,
    const float* __restrict__ B_tasks,
    const float* __restrict__ task_scales,
    float* __restrict__ out)
{
    extern __shared__ char dsm[];
    const uint32_t raw = smem_u32(dsm);
    const uint32_t base = (raw + 1023u) & ~1023u;
    char* sm = dsm + (base - raw);

    const int tid = threadIdx.x, wid = tid >> 5, lane = tid & 31;
    const int wm = wid >> 2, wn = wid & 3;      // 2 x 4 warps, warp tile 64x64
    const int m0 = blockIdx.y * BM, n0 = blockIdx.x * BN;

    // ---- cp.async: thread -> row tid>>3 (0..31), 16B chunk tid&7 ----------
    const int trow = tid >> 3, tch = tid & 7;
    const uint32_t dsw = tswz64(trow, tch);     // swz(row+32p) = swz(row)+p*4096
    const __nv_bfloat16* xh = g_xhi + (size_t)(m0 + trow) * DK + tch * 8;
    const __nv_bfloat16* xl = g_xlo + (size_t)(m0 + trow) * DK + tch * 8;
    const __nv_bfloat16* wh = g_whi + (size_t)(n0 + trow) * DK + tch * 8;
    const __nv_bfloat16* wl = g_wlo + (size_t)(n0 + trow) * DK + tch * 8;

    auto issue = [&](int chunk) {
        const uint32_t sb = base + (chunk & (NSTAGE - 1)) * STAGE_B;
        const int ko = chunk * BK;
#pragma unroll
        for (int p = 0; p < 4; p++) {
            cp16(sb + OFF_XHI + p * 4096 + dsw, xh + (size_t)p * 32 * DK + ko);
            cp16(sb + OFF_XLO + p * 4096 + dsw, xl + (size_t)p * 32 * DK + ko);
        }
#pragma unroll
        for (int p = 0; p < 8; p++) {
            cp16(sb + OFF_WHI + p * 4096 + dsw, wh + (size_t)p * 32 * DK + ko);
            cp16(sb + OFF_WLO + p * 4096 + dsw, wl + (size_t)p * 32 * DK + ko);
        }
        cp_commit();
    };

    issue(0);

    float c[8][4][4];
#pragma unroll
    for (int j = 0; j < 8; j++)
#pragma unroll
        for (int i = 0; i < 4; i++)
#pragma unroll
            for (int q = 0; q < 4; q++) c[j][i][q] = 0.f;

    // ldmatrix per-lane address components (128B rows)
    const int qrow = lane & 7, q = lane >> 3;
    const int a_row_off = wm * 64 + (q & 1) * 8 + qrow;       // + i*16
    const int a_ch_off = q >> 1;                              // + ks*2
    // B j-pair ldsm4: lanes 0-7 -> (j,k0), 8-15 -> (j,k1),
    //                 16-23 -> (j+1,k0), 24-31 -> (j+1,k1)
    const int b_row_off = wn * 64 + ((lane >> 4) << 3) + (lane & 7);  // + jp*16
    const int b_ch_off = (lane >> 3) & 1;                     // + ks*2

    for (int it = 0; it < NCHUNK; it++) {
        cp_wait<0>();
        __syncthreads();
        if (it + 1 < NCHUNK) issue(it + 1);   // overlaps all of compute(it)
        const uint32_t sb = base + (it & (NSTAGE - 1)) * STAGE_B;
#pragma unroll
        for (int ks = 0; ks < 4; ks++) {
            uint32_t ahi[4][4], alo[4][4];
#pragma unroll
            for (int i = 0; i < 4; i++) {
                const int row = a_row_off + i * 16;
                const uint32_t o = tswz64(row, ks * 2 + a_ch_off);
                ldsm4(ahi[i][0], ahi[i][1], ahi[i][2], ahi[i][3],
                      sb + OFF_XHI + o);
                ldsm4(alo[i][0], alo[i][1], alo[i][2], alo[i][3],
                      sb + OFF_XLO + o);
            }
            // B fragment double-buffer: load jp+1 before MMAs of jp
            uint32_t bh[2][4], bl[2][4];
            {
                const uint32_t o = tswz64(b_row_off, ks * 2 + b_ch_off);
                ldsm4(bh[0][0], bh[0][1], bh[0][2], bh[0][3], sb + OFF_WHI + o);
                ldsm4(bl[0][0], bl[0][1], bl[0][2], bl[0][3], sb + OFF_WLO + o);
            }
#pragma unroll
            for (int jp = 0; jp < 4; jp++) {
                const int cur = jp & 1, nxt = cur ^ 1;
                if (jp < 3) {
                    const int row = b_row_off + (jp + 1) * 16;
                    const uint32_t o = tswz64(row, ks * 2 + b_ch_off);
                    ldsm4(bh[nxt][0], bh[nxt][1], bh[nxt][2], bh[nxt][3],
                          sb + OFF_WHI + o);
                    ldsm4(bl[nxt][0], bl[nxt][1], bl[nxt][2], bl[nxt][3],
                          sb + OFF_WLO + o);
                }
                // term-outer order: same-accumulator distance = 8 MMAs
#pragma unroll
                for (int jj = 0; jj < 2; jj++)
#pragma unroll
                    for (int i = 0; i < 4; i++)
                        mma_bf16(c[jp * 2 + jj][i], ahi[i], bh[cur] + 2 * jj);
#pragma unroll
                for (int jj = 0; jj < 2; jj++)
#pragma unroll
                    for (int i = 0; i < 4; i++)
                        mma_bf16(c[jp * 2 + jj][i], ahi[i], bl[cur] + 2 * jj);
#pragma unroll
                for (int jj = 0; jj < 2; jj++)
#pragma unroll
                    for (int i = 0; i < 4; i++)
                        mma_bf16(c[jp * 2 + jj][i], alo[i], bh[cur] + 2 * jj);
            }
        }
    }
    __syncthreads();

    // ---- bias ------------------------------------------------------------
#pragma unroll
    for (int j = 0; j < 8; j++) {
        const int col = n0 + wn * 64 + j * 8 + (lane & 3) * 2;
        const float b0 = __ldg(bias + col);
        const float b1 = __ldg(bias + col + 1);
#pragma unroll
        for (int i = 0; i < 4; i++) {
            c[j][i][0] += b0; c[j][i][1] += b1;
            c[j][i][2] += b0; c[j][i][3] += b1;
        }
    }

    // ---- epilogue: stage Y[128x80] and scaled B_all[256x80] once ----------
    float* Ys = reinterpret_cast<float*>(sm);
    float* Bs = reinterpret_cast<float*>(sm + EPI_B_OFF);
    {
        const int srow = tid >> 1, half = tid & 1;
        const float* ys = g_Y + (size_t)(m0 + srow) * 80 + half * 40;
        float* yd = Ys + srow * EST + half * 40;
#pragma unroll
        for (int g = 0; g < 10; g++) {
            float4 v = __ldg(reinterpret_cast<const float4*>(ys + g * 4));
            yd[g * 4 + 0] = tf32f(v.x); yd[g * 4 + 1] = tf32f(v.y);
            yd[g * 4 + 2] = tf32f(v.z); yd[g * 4 + 3] = tf32f(v.w);
        }
        float sc[4];
#pragma unroll
        for (int t = 0; t < 4; t++) sc[t] = __ldg(task_scales + t);
        // one thread per B row (256 rows)
        float* bd = Bs + tid * EST;
#pragma unroll
        for (int g = 0; g < 20; g++) {
            const int k0 = g * 4;
            const float* src;
            float s;
            if (k0 < 16) { src = B_sh + (size_t)(n0 + tid) * 16 + k0; s = 1.f; }
            else {
                const int t = (k0 - 16) >> 4, rr = (k0 - 16) & 15;
                src = B_tasks + ((size_t)t * OK + n0 + tid) * 16 + rr;
                s = sc[t];
            }
            float4 v = __ldg(reinterpret_cast<const float4*>(src));
            bd[g * 4 + 0] = tf32f(v.x * s); bd[g * 4 + 1] = tf32f(v.y * s);
            bd[g * 4 + 2] = tf32f(v.z * s); bd[g * 4 + 3] = tf32f(v.w * s);
        }
    }
    __syncthreads();

    const int ar = wm * 64 + (lane >> 2);
    const int kk = lane & 3;
    for (int h = 0; h < 5; h++) {
        uint32_t ya[4][2][4];
#pragma unroll
        for (int i = 0; i < 4; i++)
#pragma unroll
            for (int ks = 0; ks < 2; ks++) {
                const float* bp = &Ys[(ar + i * 16) * EST + h * 16 + ks * 8 + kk];
                ya[i][ks][0] = __float_as_uint(bp[0]);
                ya[i][ks][1] = __float_as_uint(bp[8 * EST]);
                ya[i][ks][2] = __float_as_uint(bp[4]);
                ya[i][ks][3] = __float_as_uint(bp[8 * EST + 4]);
            }
        float* outh = out + (size_t)h * MTOT * OK;
#pragma unroll
        for (int j = 0; j < 8; j++) {
            uint32_t yb[2][2];
            const int bn = wn * 64 + j * 8 + (lane >> 2);
#pragma unroll
            for (int ks = 0; ks < 2; ks++) {
                const float* bp = &Bs[bn * EST + h * 16 + ks * 8 + kk];
                yb[ks][0] = __float_as_uint(bp[0]);
                yb[ks][1] = __float_as_uint(bp[4]);
            }
            const int colb = n0 + wn * 64 + j * 8 + (lane & 3) * 2;
#pragma unroll
            for (int i = 0; i < 4; i++) {
                float corr[4];
                mma_tf32_dc(corr, c[j][i], ya[i][0], yb[0]);
                mma_tf32(corr, ya[i][1], yb[1]);
                const int r0 = m0 + wm * 64 + i * 16 + (lane >> 2);
                *reinterpret_cast<float2*>(outh + (size_t)r0 * OK + colb) =
                    make_float2(corr[0], corr[1]);
                *reinterpret_cast<float2*>(outh + (size_t)(r0 + 8) * OK + colb) =
                    make_float2(corr[2], corr[3]);
            }
        }
    }
}

// ---------------------------------------------------------------------------
extern "C" void kernel_launch(void* const* d_in, const int* in_sizes, int n_in,
                              void* d_out, int out_size) {
    const float* x           = (const float*)d_in[0];
    const float* W           = (const float*)d_in[1];
    const float* b           = (const float*)d_in[2];
    const float* A_sh        = (const float*)d_in[3];
    const float* B_sh        = (const float*)d_in[4];
    const float* A_tasks     = (const float*)d_in[5];
    const float* B_tasks     = (const float*)d_in[6];
    const float* task_scales = (const float*)d_in[7];
    float* out = (float*)d_out;
    (void)in_sizes; (void)n_in; (void)out_size;

    cudaFuncSetAttribute(fused_main, cudaFuncAttributeMaxDynamicSharedMemorySize,
                         SMEM_DYN);

    prep_wk<<<OK * DK / 2048, 256>>>(W);
    lora_y_kernel<<<MTOT / BM, 256>>>(x, A_sh, A_tasks);
    fused_main<<<dim3(OK / BN, MTOT / BM), 256, SMEM_DYN>>>(
        b, B_sh, B_tasks, task_scales, out);
}

// round 13
// speedup vs baseline: 1.2183x; 1.2183x over previous
#include <cuda_runtime.h>
#include <cuda_bf16.h>
#include <cstdint>

// ===========================================================================
// MTLoRALinear on sm_103a — single-pass tf32 mainloop (R13).
// Calibration: tf32 m16n8k8 issues at the same per-instruction rate as bf16
// m16n8k16 (R1: 283 vs 574 TF/s). One tf32 pass = 128 instr per warp-32K vs
// 192 for bf16 3-term => 33% fewer tensor cycles, same smem bytes.
// Operands pre-rounded with cvt.rna (W in prep_wt, x side-written by lora_y)
// => rel_err ~2.9e-4 (R1-measured), not raw-truncation.
//   prep_wt : W fp32 -> tf32-rounded fp32
//   lora_y  : Y[M,80] = x @ concat(A_sh,A_tasks)^T (tf32) AND x -> g_xt
//   fused   : P = x@W^T single tf32 pass, BM128 BN256 BK32, 4-stage cp.async
//             + ldmatrix(b16 tiles == tf32 fragments); epilogue: bias + 5
//             rank-16 tf32 corrections + streamed stores.
// ===========================================================================

namespace {
constexpr int MTOT = 32768, DK = 1024, OK = 1024;
constexpr int BM = 128, BN = 256, BK = 32;
constexpr int NCHUNK = DK / BK;           // 32
constexpr int NSTAGE = 4;
// stage layout (128B rows of 32 f32): x(16K) w(32K) = 48KB
constexpr int OFF_X = 0, OFF_W = 16384;
constexpr int STAGE_B = 49152;
constexpr int SMEM_DYN = NSTAGE * STAGE_B + 1024;   // 197632
constexpr int XST = 36;                   // lora_y smem stride
constexpr int EST = 84;                   // epilogue stride (conflict-free)
constexpr int EPI_B_OFF = 43520;          // Ys: 128*84*4=43008, Bs after
}

__device__ __align__(256) float g_xt[MTOT * DK];   // tf32-rounded x
__device__ __align__(256) float g_wt[OK * DK];     // tf32-rounded W
__device__ __align__(256) float g_Y[MTOT * 80];

// --------------------------- helpers ---------------------------------------
__device__ __forceinline__ uint32_t smem_u32(const void* p) {
    uint32_t a;
    asm("{ .reg .u64 t; cvta.to.shared.u64 t, %1; cvt.u32.u64 %0, t; }"
        : "=r"(a) : "l"(p));
    return a;
}
__device__ __forceinline__ void cp16(uint32_t dst, const void* src) {
    asm volatile("cp.async.cg.shared.global [%0], [%1], 16;"
                 :: "r"(dst), "l"(src) : "memory");
}
__device__ __forceinline__ void cp_commit() {
    asm volatile("cp.async.commit_group;" ::: "memory");
}
template <int N> __device__ __forceinline__ void cp_wait() {
    asm volatile("cp.async.wait_group %0;" :: "n"(N) : "memory");
}
__device__ __forceinline__ void ldsm4(uint32_t& r0, uint32_t& r1, uint32_t& r2,
                                      uint32_t& r3, uint32_t a) {
    asm volatile("ldmatrix.sync.aligned.m8n8.x4.shared.b16 {%0,%1,%2,%3}, [%4];"
                 : "=r"(r0), "=r"(r1), "=r"(r2), "=r"(r3) : "r"(a));
}
__device__ __forceinline__ uint32_t tf32_rna(float x) {
    uint32_t u;
    asm("cvt.rna.tf32.f32 %0, %1;" : "=r"(u) : "f"(x));
    return u;
}
__device__ __forceinline__ float tf32f(float x) {
    return __uint_as_float(tf32_rna(x));
}
__device__ __forceinline__ void mma_tf32(float* c, const uint32_t* a,
                                         const uint32_t* b) {
    asm volatile(
        "mma.sync.aligned.m16n8k8.row.col.f32.tf32.tf32.f32 "
        "{%0,%1,%2,%3}, {%4,%5,%6,%7}, {%8,%9}, {%0,%1,%2,%3};"
        : "+f"(c[0]), "+f"(c[1]), "+f"(c[2]), "+f"(c[3])
        : "r"(a[0]), "r"(a[1]), "r"(a[2]), "r"(a[3]), "r"(b[0]), "r"(b[1]));
}
__device__ __forceinline__ void mma_tf32_dc(float* d, const float* c,
                                            const uint32_t* a, const uint32_t* b) {
    asm volatile(
        "mma.sync.aligned.m16n8k8.row.col.f32.tf32.tf32.f32 "
        "{%0,%1,%2,%3}, {%4,%5,%6,%7}, {%8,%9}, {%10,%11,%12,%13};"
        : "=f"(d[0]), "=f"(d[1]), "=f"(d[2]), "=f"(d[3])
        : "r"(a[0]), "r"(a[1]), "r"(a[2]), "r"(a[3]), "r"(b[0]), "r"(b[1]),
          "f"(c[0]), "f"(c[1]), "f"(c[2]), "f"(c[3]));
}
// 128B-row tile, 8x16B chunks, XOR-8 swizzle (R4/R11-proven conflict-free)
__device__ __forceinline__ uint32_t tswz64(int row, int ch) {
    return (uint32_t)(row * 128 + ((ch ^ (row & 7)) << 4));
}

// --------------------------- prep W (tf32 round) ---------------------------
__global__ __launch_bounds__(256) void prep_wt(const float* __restrict__ W) {
    size_t i = ((size_t)blockIdx.x * 256 + threadIdx.x) * 4;
    float4 v = *reinterpret_cast<const float4*>(W + i);
    v.x = tf32f(v.x); v.y = tf32f(v.y); v.z = tf32f(v.z); v.w = tf32f(v.w);
    *reinterpret_cast<float4*>(g_wt + i) = v;
}

// ---------------- lora_y + side-write x -> tf32-rounded --------------------
__global__ __launch_bounds__(256) void lora_y_kernel(
    const float* __restrict__ x,
    const float* __restrict__ A_sh,
    const float* __restrict__ A_tasks)
{
    __shared__ float Xs[BM * XST];
    __shared__ float Ws[BM * XST];

    const int tid = threadIdx.x;
    const int lane = tid & 31, wid = tid >> 5;
    const int wm = wid >> 2, wn = wid & 3;
    const int m0 = blockIdx.x * BM;
    const int lr = tid >> 3;
    const int lc = (tid & 7) << 2;

    const float* xg = x + (size_t)(m0 + lr) * DK + lc;
    const float* ag[4];
    bool av[4];
#pragma unroll
    for (int i = 0; i < 4; i++) {
        const int r = lr + 32 * i;
        if (r < 16)      { ag[i] = A_sh + (size_t)r * DK + lc; av[i] = true; }
        else if (r < 80) { ag[i] = A_tasks + (size_t)(r - 16) * DK + lc; av[i] = true; }
        else             { ag[i] = A_sh + lc; av[i] = false; }
    }

    float4 px[4], pw[4];
    const float4 z4 = make_float4(0.f, 0.f, 0.f, 0.f);
#pragma unroll
    for (int i = 0; i < 4; i++) {
        px[i] = *reinterpret_cast<const float4*>(xg + (size_t)(32 * i) * DK);
        pw[i] = av[i] ? *reinterpret_cast<const float4*>(ag[i]) : z4;
    }

    float c[4][4][4];
#pragma unroll
    for (int i = 0; i < 4; i++)
#pragma unroll
        for (int j = 0; j < 4; j++)
#pragma unroll
            for (int q = 0; q < 4; q++) c[i][j][q] = 0.f;

    for (int kc = 0; kc < DK; kc += 32) {
        __syncthreads();
#pragma unroll
        for (int i = 0; i < 4; i++) {
            float4 xr = make_float4(tf32f(px[i].x), tf32f(px[i].y),
                                    tf32f(px[i].z), tf32f(px[i].w));
            // side product: tf32-rounded x (each element written exactly once)
            *reinterpret_cast<float4*>(
                g_xt + (size_t)(m0 + lr + 32 * i) * DK + kc + lc) = xr;
            float* xs = &Xs[(lr + 32 * i) * XST + lc];
            xs[0] = xr.x; xs[1] = xr.y; xs[2] = xr.z; xs[3] = xr.w;
            float* ws = &Ws[(lr + 32 * i) * XST + lc];
            ws[0] = tf32f(pw[i].x); ws[1] = tf32f(pw[i].y);
            ws[2] = tf32f(pw[i].z); ws[3] = tf32f(pw[i].w);
        }
        __syncthreads();
        if (kc + 32 < DK) {
#pragma unroll
            for (int i = 0; i < 4; i++) {
                px[i] = *reinterpret_cast<const float4*>(xg + (size_t)(32 * i) * DK + kc + 32);
                pw[i] = av[i] ? *reinterpret_cast<const float4*>(ag[i] + kc + 32) : z4;
            }
        }
#pragma unroll
        for (int ks = 0; ks < 4; ks++) {
            const int ak = ks * 8 + (lane & 3);
            const int ar = wm * 64 + (lane >> 2);
            uint32_t a[4][4];
#pragma unroll
            for (int i = 0; i < 4; i++) {
                const float* base = &Xs[(ar + i * 16) * XST + ak];
                a[i][0] = __float_as_uint(base[0]);
                a[i][1] = __float_as_uint(base[8 * XST]);
                a[i][2] = __float_as_uint(base[4]);
                a[i][3] = __float_as_uint(base[8 * XST + 4]);
            }
            uint32_t b[4][2];
            const int bn = wn * 32 + (lane >> 2);
#pragma unroll
            for (int j = 0; j < 4; j++) {
                const float* base = &Ws[(bn + j * 8) * XST + ak];
                b[j][0] = __float_as_uint(base[0]);
                b[j][1] = __float_as_uint(base[4]);
            }
#pragma unroll
            for (int i = 0; i < 4; i++)
#pragma unroll
                for (int j = 0; j < 4; j++)
                    mma_tf32(c[i][j], a[i], b[j]);
        }
    }

#pragma unroll
    for (int j = 0; j < 4; j++) {
        const int colb = wn * 32 + j * 8 + (lane & 3) * 2;
        if (colb < 80) {
#pragma unroll
            for (int i = 0; i < 4; i++) {
                const int r0 = m0 + wm * 64 + i * 16 + (lane >> 2);
                *reinterpret_cast<float2*>(g_Y + (size_t)r0 * 80 + colb) =
                    make_float2(c[i][j][0], c[i][j][1]);
                *reinterpret_cast<float2*>(g_Y + (size_t)(r0 + 8) * 80 + colb) =
                    make_float2(c[i][j][2], c[i][j][3]);
            }
        }
    }
}

// --------------------------- fused main ------------------------------------
__global__ __launch_bounds__(256, 1) void fused_main(
    const float* __restrict__ bias,
    const float* __restrict__ B_sh,
    const float* __restrict__ B_tasks,
    const float* __restrict__ task_scales,
    float* __restrict__ out)
{
    extern __shared__ char dsm[];
    const uint32_t raw = smem_u32(dsm);
    const uint32_t base = (raw + 1023u) & ~1023u;
    char* sm = dsm + (base - raw);

    const int tid = threadIdx.x, wid = tid >> 5, lane = tid & 31;
    const int wm = wid >> 2, wn = wid & 3;      // 2 x 4 warps, warp tile 64x64
    const int m0 = blockIdx.y * BM, n0 = blockIdx.x * BN;

    // ---- cp.async: thread -> row tid>>3 (0..31), 16B chunk tid&7 ----------
    // rows step by 32: x tile 128 rows (4 pages), w tile 256 rows (8 pages)
    const int trow = tid >> 3, tch = tid & 7;
    const uint32_t dsw = tswz64(trow, tch);     // swz(row+32p) = swz(row)+p*4096
    const float* xp = g_xt + (size_t)(m0 + trow) * DK + tch * 4;
    const float* wp = g_wt + (size_t)(n0 + trow) * DK + tch * 4;

    auto issue = [&](int chunk) {
        const uint32_t sb = base + (chunk & (NSTAGE - 1)) * STAGE_B;
        const int ko = chunk * BK;
#pragma unroll
        for (int p = 0; p < 4; p++)
            cp16(sb + OFF_X + p * 4096 + dsw, xp + (size_t)p * 32 * DK + ko);
#pragma unroll
        for (int p = 0; p < 8; p++)
            cp16(sb + OFF_W + p * 4096 + dsw, wp + (size_t)p * 32 * DK + ko);
        cp_commit();
    };

    issue(0); issue(1); issue(2);

    float c[8][4][4];
#pragma unroll
    for (int j = 0; j < 8; j++)
#pragma unroll
        for (int i = 0; i < 4; i++)
#pragma unroll
            for (int q = 0; q < 4; q++) c[j][i][q] = 0.f;

    // ldmatrix lane address components (b16 m8n8 tile == tf32 fragment)
    const int qrow = lane & 7, q = lane >> 3;
    const int a_row_off = wm * 64 + (q & 1) * 8 + qrow;       // + i*16
    const int a_ch_off = q >> 1;                              // + ks*2
    // B j-pair ldsm4: lanes 0-7 -> (j,b0), 8-15 -> (j,b1),
    //                 16-23 -> (j+1,b0), 24-31 -> (j+1,b1)
    const int b_row_off = wn * 64 + ((lane >> 4) << 3) + (lane & 7);  // + jp*16
    const int b_ch_off = (lane >> 3) & 1;                     // + ks*2

    for (int it = 0; it < NCHUNK; it++) {
        cp_wait<2>();
        __syncthreads();
        if (it + 3 < NCHUNK) issue(it + 3);   // overlaps compute
        else cp_commit();
        const uint32_t sb = base + (it & (NSTAGE - 1)) * STAGE_B;
#pragma unroll
        for (int ks = 0; ks < 4; ks++) {      // 4 k8-steps per 32-K chunk
            uint32_t a[4][4];
#pragma unroll
            for (int i = 0; i < 4; i++) {
                const int row = a_row_off + i * 16;
                const uint32_t o = tswz64(row, ks * 2 + a_ch_off);
                ldsm4(a[i][0], a[i][1], a[i][2], a[i][3], sb + OFF_X + o);
            }
#pragma unroll
            for (int jp = 0; jp < 4; jp++) {
                const int row = b_row_off + jp * 16;
                const uint32_t o = tswz64(row, ks * 2 + b_ch_off);
                uint32_t b[4];
                ldsm4(b[0], b[1], b[2], b[3], sb + OFF_W + o);
#pragma unroll
                for (int jj = 0; jj < 2; jj++)
#pragma unroll
                    for (int i = 0; i < 4; i++)
                        mma_tf32(c[jp * 2 + jj][i], a[i], b + 2 * jj);
            }
        }
    }
    cp_wait<0>();
    __syncthreads();

    // ---- bias ------------------------------------------------------------
#pragma unroll
    for (int j = 0; j < 8; j++) {
        const int col = n0 + wn * 64 + j * 8 + (lane & 3) * 2;
        const float b0 = __ldg(bias + col);
        const float b1 = __ldg(bias + col + 1);
#pragma unroll
        for (int i = 0; i < 4; i++) {
            c[j][i][0] += b0; c[j][i][1] += b1;
            c[j][i][2] += b0; c[j][i][3] += b1;
        }
    }

    // ---- epilogue: stage Y[128x80] and scaled B_all[256x80] once ----------
    float* Ys = reinterpret_cast<float*>(sm);
    float* Bs = reinterpret_cast<float*>(sm + EPI_B_OFF);
    {
        const int srow = tid >> 1, half = tid & 1;
        const float* ys = g_Y + (size_t)(m0 + srow) * 80 + half * 40;
        float* yd = Ys + srow * EST + half * 40;
#pragma unroll
        for (int g = 0; g < 10; g++) {
            float4 v = __ldg(reinterpret_cast<const float4*>(ys + g * 4));
            yd[g * 4 + 0] = tf32f(v.x); yd[g * 4 + 1] = tf32f(v.y);
            yd[g * 4 + 2] = tf32f(v.z); yd[g * 4 + 3] = tf32f(v.w);
        }
        float sc[4];
#pragma unroll
        for (int t = 0; t < 4; t++) sc[t] = __ldg(task_scales + t);
        // one thread per B row (256 rows)
        float* bd = Bs + tid * EST;
#pragma unroll
        for (int g = 0; g < 20; g++) {
            const int k0 = g * 4;
            const float* src;
            float s;
            if (k0 < 16) { src = B_sh + (size_t)(n0 + tid) * 16 + k0; s = 1.f; }
            else {
                const int t = (k0 - 16) >> 4, rr = (k0 - 16) & 15;
                src = B_tasks + ((size_t)t * OK + n0 + tid) * 16 + rr;
                s = sc[t];
            }
            float4 v = __ldg(reinterpret_cast<const float4*>(src));
            bd[g * 4 + 0] = tf32f(v.x * s); bd[g * 4 + 1] = tf32f(v.y * s);
            bd[g * 4 + 2] = tf32f(v.z * s); bd[g * 4 + 3] = tf32f(v.w * s);
        }
    }
    __syncthreads();

    const int ar = wm * 64 + (lane >> 2);
    const int kk = lane & 3;
    for (int h = 0; h < 5; h++) {
        uint32_t ya[4][2][4];
#pragma unroll
        for (int i = 0; i < 4; i++)
#pragma unroll
            for (int ks = 0; ks < 2; ks++) {
                const float* bp = &Ys[(ar + i * 16) * EST + h * 16 + ks * 8 + kk];
                ya[i][ks][0] = __float_as_uint(bp[0]);
                ya[i][ks][1] = __float_as_uint(bp[8 * EST]);
                ya[i][ks][2] = __float_as_uint(bp[4]);
                ya[i][ks][3] = __float_as_uint(bp[8 * EST + 4]);
            }
        float* outh = out + (size_t)h * MTOT * OK;
#pragma unroll
        for (int j = 0; j < 8; j++) {
            uint32_t yb[2][2];
            const int bn = wn * 64 + j * 8 + (lane >> 2);
#pragma unroll
            for (int ks = 0; ks < 2; ks++) {
                const float* bp = &Bs[bn * EST + h * 16 + ks * 8 + kk];
                yb[ks][0] = __float_as_uint(bp[0]);
                yb[ks][1] = __float_as_uint(bp[4]);
            }
            const int colb = n0 + wn * 64 + j * 8 + (lane & 3) * 2;
#pragma unroll
            for (int i = 0; i < 4; i++) {
                float corr[4];
                mma_tf32_dc(corr, c[j][i], ya[i][0], yb[0]);
                mma_tf32(corr, ya[i][1], yb[1]);
                const int r0 = m0 + wm * 64 + i * 16 + (lane >> 2);
                *reinterpret_cast<float2*>(outh + (size_t)r0 * OK + colb) =
                    make_float2(corr[0], corr[1]);
                *reinterpret_cast<float2*>(outh + (size_t)(r0 + 8) * OK + colb) =
                    make_float2(corr[2], corr[3]);
            }
        }
    }
}

// ---------------------------------------------------------------------------
extern "C" void kernel_launch(void* const* d_in, const int* in_sizes, int n_in,
                              void* d_out, int out_size) {
    const float* x           = (const float*)d_in[0];
    const float* W           = (const float*)d_in[1];
    const float* b           = (const float*)d_in[2];
    const float* A_sh        = (const float*)d_in[3];
    const float* B_sh        = (const float*)d_in[4];
    const float* A_tasks     = (const float*)d_in[5];
    const float* B_tasks     = (const float*)d_in[6];
    const float* task_scales = (const float*)d_in[7];
    float* out = (float*)d_out;
    (void)in_sizes; (void)n_in; (void)out_size;

    cudaFuncSetAttribute(fused_main, cudaFuncAttributeMaxDynamicSharedMemorySize,
                         SMEM_DYN);

    prep_wt<<<OK * DK / 1024, 256>>>(W);
    lora_y_kernel<<<MTOT / BM, 256>>>(x, A_sh, A_tasks);
    fused_main<<<dim3(OK / BN, MTOT / BM), 256, SMEM_DYN>>>(
        b, B_sh, B_tasks, task_scales, out);
}

// round 14
// speedup vs baseline: 1.2340x; 1.0129x over previous
#include <cuda_runtime.h>
#include <cuda_bf16.h>
#include <cstdint>

// ===========================================================================
// MTLoRALinear on sm_103a — single-pass tf32 mainloop, BK=64 (R14).
// R13 (tf32 single pass, 519us) + R11's proven chunk amortization: BK 32->64,
// 2-stage x 96KB pipeline, issue-before-compute. 16 sync points instead of 32.
//   prep_wt : W fp32 -> tf32-rounded fp32
//   lora_y  : Y[M,80] = x @ concat(A_sh,A_tasks)^T (tf32) AND x -> g_xt
//   fused   : P = x@W^T single tf32 pass, BM128 BN256 BK64; epilogue: bias +
//             5 rank-16 tf32 corrections + streamed stores.
// ===========================================================================

namespace {
constexpr int MTOT = 32768, DK = 1024, OK = 1024;
constexpr int BM = 128, BN = 256, BK = 64;
constexpr int NCHUNK = DK / BK;           // 16
constexpr int NSTAGE = 2;
// stage layout (256B rows of 64 f32): x(32K) w(64K) = 96KB
constexpr int OFF_X = 0, OFF_W = 32768;
constexpr int STAGE_B = 98304;
constexpr int SMEM_DYN = NSTAGE * STAGE_B + 1024;   // 197632
constexpr int XST = 36;                   // lora_y smem stride
constexpr int EST = 84;                   // epilogue stride (conflict-free)
constexpr int EPI_B_OFF = 43520;          // Ys: 128*84*4=43008, Bs after
}

__device__ __align__(256) float g_xt[MTOT * DK];   // tf32-rounded x
__device__ __align__(256) float g_wt[OK * DK];     // tf32-rounded W
__device__ __align__(256) float g_Y[MTOT * 80];

// --------------------------- helpers ---------------------------------------
__device__ __forceinline__ uint32_t smem_u32(const void* p) {
    uint32_t a;
    asm("{ .reg .u64 t; cvta.to.shared.u64 t, %1; cvt.u32.u64 %0, t; }"
        : "=r"(a) : "l"(p));
    return a;
}
__device__ __forceinline__ void cp16(uint32_t dst, const void* src) {
    asm volatile("cp.async.cg.shared.global [%0], [%1], 16;"
                 :: "r"(dst), "l"(src) : "memory");
}
__device__ __forceinline__ void cp_commit() {
    asm volatile("cp.async.commit_group;" ::: "memory");
}
template <int N> __device__ __forceinline__ void cp_wait() {
    asm volatile("cp.async.wait_group %0;" :: "n"(N) : "memory");
}
__device__ __forceinline__ void ldsm4(uint32_t& r0, uint32_t& r1, uint32_t& r2,
                                      uint32_t& r3, uint32_t a) {
    asm volatile("ldmatrix.sync.aligned.m8n8.x4.shared.b16 {%0,%1,%2,%3}, [%4];"
                 : "=r"(r0), "=r"(r1), "=r"(r2), "=r"(r3) : "r"(a));
}
__device__ __forceinline__ uint32_t tf32_rna(float x) {
    uint32_t u;
    asm("cvt.rna.tf32.f32 %0, %1;" : "=r"(u) : "f"(x));
    return u;
}
__device__ __forceinline__ float tf32f(float x) {
    return __uint_as_float(tf32_rna(x));
}
__device__ __forceinline__ void mma_tf32(float* c, const uint32_t* a,
                                         const uint32_t* b) {
    asm volatile(
        "mma.sync.aligned.m16n8k8.row.col.f32.tf32.tf32.f32 "
        "{%0,%1,%2,%3}, {%4,%5,%6,%7}, {%8,%9}, {%0,%1,%2,%3};"
        : "+f"(c[0]), "+f"(c[1]), "+f"(c[2]), "+f"(c[3])
        : "r"(a[0]), "r"(a[1]), "r"(a[2]), "r"(a[3]), "r"(b[0]), "r"(b[1]));
}
__device__ __forceinline__ void mma_tf32_dc(float* d, const float* c,
                                            const uint32_t* a, const uint32_t* b) {
    asm volatile(
        "mma.sync.aligned.m16n8k8.row.col.f32.tf32.tf32.f32 "
        "{%0,%1,%2,%3}, {%4,%5,%6,%7}, {%8,%9}, {%10,%11,%12,%13};"
        : "=f"(d[0]), "=f"(d[1]), "=f"(d[2]), "=f"(d[3])
        : "r"(a[0]), "r"(a[1]), "r"(a[2]), "r"(a[3]), "r"(b[0]), "r"(b[1]),
          "f"(c[0]), "f"(c[1]), "f"(c[2]), "f"(c[3]));
}
// 256B-row tile (64 f32), 16x16B chunks, XOR-8 swizzle.
// ldsm reads 8 consecutive rows at fixed ch -> 8 distinct 16B slots mod 128B:
// conflict-free (same argument as the 128B-row variant, proven R4/R11/R13).
__device__ __forceinline__ uint32_t tswz128(int row, int ch) {
    return (uint32_t)(row * 256 + ((ch ^ (row & 7)) << 4));
}

// --------------------------- prep W (tf32 round) ---------------------------
__global__ __launch_bounds__(256) void prep_wt(const float* __restrict__ W) {
    size_t i = ((size_t)blockIdx.x * 256 + threadIdx.x) * 4;
    float4 v = *reinterpret_cast<const float4*>(W + i);
    v.x = tf32f(v.x); v.y = tf32f(v.y); v.z = tf32f(v.z); v.w = tf32f(v.w);
    *reinterpret_cast<float4*>(g_wt + i) = v;
}

// ---------------- lora_y + side-write x -> tf32-rounded --------------------
__global__ __launch_bounds__(256) void lora_y_kernel(
    const float* __restrict__ x,
    const float* __restrict__ A_sh,
    const float* __restrict__ A_tasks)
{
    __shared__ float Xs[BM * XST];
    __shared__ float Ws[BM * XST];

    const int tid = threadIdx.x;
    const int lane = tid & 31, wid = tid >> 5;
    const int wm = wid >> 2, wn = wid & 3;
    const int m0 = blockIdx.x * BM;
    const int lr = tid >> 3;
    const int lc = (tid & 7) << 2;

    const float* xg = x + (size_t)(m0 + lr) * DK + lc;
    const float* ag[4];
    bool av[4];
#pragma unroll
    for (int i = 0; i < 4; i++) {
        const int r = lr + 32 * i;
        if (r < 16)      { ag[i] = A_sh + (size_t)r * DK + lc; av[i] = true; }
        else if (r < 80) { ag[i] = A_tasks + (size_t)(r - 16) * DK + lc; av[i] = true; }
        else             { ag[i] = A_sh + lc; av[i] = false; }
    }

    float4 px[4], pw[4];
    const float4 z4 = make_float4(0.f, 0.f, 0.f, 0.f);
#pragma unroll
    for (int i = 0; i < 4; i++) {
        px[i] = *reinterpret_cast<const float4*>(xg + (size_t)(32 * i) * DK);
        pw[i] = av[i] ? *reinterpret_cast<const float4*>(ag[i]) : z4;
    }

    float c[4][4][4];
#pragma unroll
    for (int i = 0; i < 4; i++)
#pragma unroll
        for (int j = 0; j < 4; j++)
#pragma unroll
            for (int q = 0; q < 4; q++) c[i][j][q] = 0.f;

    for (int kc = 0; kc < DK; kc += 32) {
        __syncthreads();
#pragma unroll
        for (int i = 0; i < 4; i++) {
            float4 xr = make_float4(tf32f(px[i].x), tf32f(px[i].y),
                                    tf32f(px[i].z), tf32f(px[i].w));
            *reinterpret_cast<float4*>(
                g_xt + (size_t)(m0 + lr + 32 * i) * DK + kc + lc) = xr;
            float* xs = &Xs[(lr + 32 * i) * XST + lc];
            xs[0] = xr.x; xs[1] = xr.y; xs[2] = xr.z; xs[3] = xr.w;
            float* ws = &Ws[(lr + 32 * i) * XST + lc];
            ws[0] = tf32f(pw[i].x); ws[1] = tf32f(pw[i].y);
            ws[2] = tf32f(pw[i].z); ws[3] = tf32f(pw[i].w);
        }
        __syncthreads();
        if (kc + 32 < DK) {
#pragma unroll
            for (int i = 0; i < 4; i++) {
                px[i] = *reinterpret_cast<const float4*>(xg + (size_t)(32 * i) * DK + kc + 32);
                pw[i] = av[i] ? *reinterpret_cast<const float4*>(ag[i] + kc + 32) : z4;
            }
        }
#pragma unroll
        for (int ks = 0; ks < 4; ks++) {
            const int ak = ks * 8 + (lane & 3);
            const int ar = wm * 64 + (lane >> 2);
            uint32_t a[4][4];
#pragma unroll
            for (int i = 0; i < 4; i++) {
                const float* base = &Xs[(ar + i * 16) * XST + ak];
                a[i][0] = __float_as_uint(base[0]);
                a[i][1] = __float_as_uint(base[8 * XST]);
                a[i][2] = __float_as_uint(base[4]);
                a[i][3] = __float_as_uint(base[8 * XST + 4]);
            }
            uint32_t b[4][2];
            const int bn = wn * 32 + (lane >> 2);
#pragma unroll
            for (int j = 0; j < 4; j++) {
                const float* base = &Ws[(bn + j * 8) * XST + ak];
                b[j][0] = __float_as_uint(base[0]);
                b[j][1] = __float_as_uint(base[4]);
            }
#pragma unroll
            for (int i = 0; i < 4; i++)
#pragma unroll
                for (int j = 0; j < 4; j++)
                    mma_tf32(c[i][j], a[i], b[j]);
        }
    }

#pragma unroll
    for (int j = 0; j < 4; j++) {
        const int colb = wn * 32 + j * 8 + (lane & 3) * 2;
        if (colb < 80) {
#pragma unroll
            for (int i = 0; i < 4; i++) {
                const int r0 = m0 + wm * 64 + i * 16 + (lane >> 2);
                *reinterpret_cast<float2*>(g_Y + (size_t)r0 * 80 + colb) =
                    make_float2(c[i][j][0], c[i][j][1]);
                *reinterpret_cast<float2*>(g_Y + (size_t)(r0 + 8) * 80 + colb) =
                    make_float2(c[i][j][2], c[i][j][3]);
            }
        }
    }
}

// --------------------------- fused main ------------------------------------
__global__ __launch_bounds__(256, 1) void fused_main(
    const float* __restrict__ bias,
    const float* __restrict__ B_sh,
    const float* __restrict__ B_tasks,
    const float* __restrict__ task_scales,
    float* __restrict__ out)
{
    extern __shared__ char dsm[];
    const uint32_t raw = smem_u32(dsm);
    const uint32_t base = (raw + 1023u) & ~1023u;
    char* sm = dsm + (base - raw);

    const int tid = threadIdx.x, wid = tid >> 5, lane = tid & 31;
    const int wm = wid >> 2, wn = wid & 3;      // 2 x 4 warps, warp tile 64x64
    const int m0 = blockIdx.y * BM, n0 = blockIdx.x * BN;

    // ---- cp.async: thread -> row tid>>3 (0..31 step by 32), chunks tid&7
    //      and (tid&7)+8 (two 16B chunks per 256B row) --------------------
    const int trow = tid >> 3, tch = tid & 7;
    const uint32_t dsw0 = tswz128(trow, tch);
    const uint32_t dsw1 = tswz128(trow, tch + 8);
    const float* xp = g_xt + (size_t)(m0 + trow) * DK + tch * 4;
    const float* wp = g_wt + (size_t)(n0 + trow) * DK + tch * 4;

    auto issue = [&](int chunk) {
        const uint32_t sb = base + (chunk & (NSTAGE - 1)) * STAGE_B;
        const int ko = chunk * BK;
#pragma unroll
        for (int p = 0; p < 4; p++) {
            const float* s = xp + (size_t)p * 32 * DK + ko;
            cp16(sb + OFF_X + p * 8192 + dsw0, s);
            cp16(sb + OFF_X + p * 8192 + dsw1, s + 32);
        }
#pragma unroll
        for (int p = 0; p < 8; p++) {
            const float* s = wp + (size_t)p * 32 * DK + ko;
            cp16(sb + OFF_W + p * 8192 + dsw0, s);
            cp16(sb + OFF_W + p * 8192 + dsw1, s + 32);
        }
        cp_commit();
    };

    issue(0);

    float c[8][4][4];
#pragma unroll
    for (int j = 0; j < 8; j++)
#pragma unroll
        for (int i = 0; i < 4; i++)
#pragma unroll
            for (int q = 0; q < 4; q++) c[j][i][q] = 0.f;

    // ldmatrix lane address components (b16 m8n8 tile == tf32 fragment)
    const int qrow = lane & 7, q = lane >> 3;
    const int a_row_off = wm * 64 + (q & 1) * 8 + qrow;       // + i*16
    const int a_ch_off = q >> 1;                              // + ks*2
    const int b_row_off = wn * 64 + ((lane >> 4) << 3) + (lane & 7);  // + jp*16
    const int b_ch_off = (lane >> 3) & 1;                     // + ks*2

    for (int it = 0; it < NCHUNK; it++) {
        cp_wait<0>();
        __syncthreads();
        if (it + 1 < NCHUNK) issue(it + 1);   // overlaps all of compute(it)
        const uint32_t sb = base + (it & (NSTAGE - 1)) * STAGE_B;
#pragma unroll
        for (int ks = 0; ks < 8; ks++) {      // 8 k8-steps per 64-K chunk
            uint32_t a[4][4];
#pragma unroll
            for (int i = 0; i < 4; i++) {
                const int row = a_row_off + i * 16;
                const uint32_t o = tswz128(row, ks * 2 + a_ch_off);
                ldsm4(a[i][0], a[i][1], a[i][2], a[i][3], sb + OFF_X + o);
            }
#pragma unroll
            for (int jp = 0; jp < 4; jp++) {
                const int row = b_row_off + jp * 16;
                const uint32_t o = tswz128(row, ks * 2 + b_ch_off);
                uint32_t b[4];
                ldsm4(b[0], b[1], b[2], b[3], sb + OFF_W + o);
#pragma unroll
                for (int jj = 0; jj < 2; jj++)
#pragma unroll
                    for (int i = 0; i < 4; i++)
                        mma_tf32(c[jp * 2 + jj][i], a[i], b + 2 * jj);
            }
        }
    }
    __syncthreads();

    // ---- bias ------------------------------------------------------------
#pragma unroll
    for (int j = 0; j < 8; j++) {
        const int col = n0 + wn * 64 + j * 8 + (lane & 3) * 2;
        const float b0 = __ldg(bias + col);
        const float b1 = __ldg(bias + col + 1);
#pragma unroll
        for (int i = 0; i < 4; i++) {
            c[j][i][0] += b0; c[j][i][1] += b1;
            c[j][i][2] += b0; c[j][i][3] += b1;
        }
    }

    // ---- epilogue: stage Y[128x80] and scaled B_all[256x80] once ----------
    float* Ys = reinterpret_cast<float*>(sm);
    float* Bs = reinterpret_cast<float*>(sm + EPI_B_OFF);
    {
        const int srow = tid >> 1, half = tid & 1;
        const float* ys = g_Y + (size_t)(m0 + srow) * 80 + half * 40;
        float* yd = Ys + srow * EST + half * 40;
#pragma unroll
        for (int g = 0; g < 10; g++) {
            float4 v = __ldg(reinterpret_cast<const float4*>(ys + g * 4));
            yd[g * 4 + 0] = tf32f(v.x); yd[g * 4 + 1] = tf32f(v.y);
            yd[g * 4 + 2] = tf32f(v.z); yd[g * 4 + 3] = tf32f(v.w);
        }
        float sc[4];
#pragma unroll
        for (int t = 0; t < 4; t++) sc[t] = __ldg(task_scales + t);
        // one thread per B row (256 rows)
        float* bd = Bs + tid * EST;
#pragma unroll
        for (int g = 0; g < 20; g++) {
            const int k0 = g * 4;
            const float* src;
            float s;
            if (k0 < 16) { src = B_sh + (size_t)(n0 + tid) * 16 + k0; s = 1.f; }
            else {
                const int t = (k0 - 16) >> 4, rr = (k0 - 16) & 15;
                src = B_tasks + ((size_t)t * OK + n0 + tid) * 16 + rr;
                s = sc[t];
            }
            float4 v = __ldg(reinterpret_cast<const float4*>(src));
            bd[g * 4 + 0] = tf32f(v.x * s); bd[g * 4 + 1] = tf32f(v.y * s);
            bd[g * 4 + 2] = tf32f(v.z * s); bd[g * 4 + 3] = tf32f(v.w * s);
        }
    }
    __syncthreads();

    const int ar = wm * 64 + (lane >> 2);
    const int kk = lane & 3;
    for (int h = 0; h < 5; h++) {
        uint32_t ya[4][2][4];
#pragma unroll
        for (int i = 0; i < 4; i++)
#pragma unroll
            for (int ks = 0; ks < 2; ks++) {
                const float* bp = &Ys[(ar + i * 16) * EST + h * 16 + ks * 8 + kk];
                ya[i][ks][0] = __float_as_uint(bp[0]);
                ya[i][ks][1] = __float_as_uint(bp[8 * EST]);
                ya[i][ks][2] = __float_as_uint(bp[4]);
                ya[i][ks][3] = __float_as_uint(bp[8 * EST + 4]);
            }
        float* outh = out + (size_t)h * MTOT * OK;
#pragma unroll
        for (int j = 0; j < 8; j++) {
            uint32_t yb[2][2];
            const int bn = wn * 64 + j * 8 + (lane >> 2);
#pragma unroll
            for (int ks = 0; ks < 2; ks++) {
                const float* bp = &Bs[bn * EST + h * 16 + ks * 8 + kk];
                yb[ks][0] = __float_as_uint(bp[0]);
                yb[ks][1] = __float_as_uint(bp[4]);
            }
            const int colb = n0 + wn * 64 + j * 8 + (lane & 3) * 2;
#pragma unroll
            for (int i = 0; i < 4; i++) {
                float corr[4];
                mma_tf32_dc(corr, c[j][i], ya[i][0], yb[0]);
                mma_tf32(corr, ya[i][1], yb[1]);
                const int r0 = m0 + wm * 64 + i * 16 + (lane >> 2);
                *reinterpret_cast<float2*>(outh + (size_t)r0 * OK + colb) =
                    make_float2(corr[0], corr[1]);
                *reinterpret_cast<float2*>(outh + (size_t)(r0 + 8) * OK + colb) =
                    make_float2(corr[2], corr[3]);
            }
        }
    }
}

// ---------------------------------------------------------------------------
extern "C" void kernel_launch(void* const* d_in, const int* in_sizes, int n_in,
                              void* d_out, int out_size) {
    const float* x           = (const float*)d_in[0];
    const float* W           = (const float*)d_in[1];
    const float* b           = (const float*)d_in[2];
    const float* A_sh        = (const float*)d_in[3];
    const float* B_sh        = (const float*)d_in[4];
    const float* A_tasks     = (const float*)d_in[5];
    const float* B_tasks     = (const float*)d_in[6];
    const float* task_scales = (const float*)d_in[7];
    float* out = (float*)d_out;
    (void)in_sizes; (void)n_in; (void)out_size;

    cudaFuncSetAttribute(fused_main, cudaFuncAttributeMaxDynamicSharedMemorySize,
                         SMEM_DYN);

    prep_wt<<<OK * DK / 1024, 256>>>(W);
    lora_y_kernel<<<MTOT / BM, 256>>>(x, A_sh, A_tasks);
    fused_main<<<dim3(OK / BN, MTOT / BM), 256, SMEM_DYN>>>(
        b, B_sh, B_tasks, task_scales, out);
}